// round 1
// baseline (speedup 1.0000x reference)
#include <cuda_runtime.h>
#include <cuda_bf16.h>

// Problem dims
#define BB 2
#define SS 2048
#define HH 1024
#define NH 16
#define DD 64
#define MM (BB * SS)       // 4096 rows
#define K3H (3 * HH)       // 3072

// Scratch (device globals; no allocation allowed)
__device__ float g_q[BB * NH * SS * DD];   // [b][n][s][d], pre-scaled by D^-0.5
__device__ float g_k[BB * NH * SS * DD];
__device__ float g_v[BB * NH * SS * DD];
__device__ float g_o[MM * HH];             // [b*s][h] with h = n*64 + d

// ---------------------------------------------------------------------------
// Kernel 1: QKV projection. C[M,3H] = X[M,H] @ W[3H,H]^T + b, scattered into
// per-head layouts g_q/g_k/g_v. Q gets the softmax scale (0.125) folded in.
// 128x128 block tile, K-tile 8, 8x8 per-thread micro-tile, 256 threads.
// ---------------------------------------------------------------------------
__global__ __launch_bounds__(256) void gemm_qkv(const float* __restrict__ X,
                                                const float* __restrict__ W,
                                                const float* __restrict__ bias)
{
    __shared__ float As[8][128];
    __shared__ float Bs[8][128];

    const int t  = threadIdx.x;
    const int tx = t & 15;
    const int ty = t >> 4;
    const int m0 = blockIdx.y * 128;
    const int n0 = blockIdx.x * 128;
    const int K  = HH;

    float acc[8][8];
#pragma unroll
    for (int i = 0; i < 8; i++)
#pragma unroll
        for (int j = 0; j < 8; j++) acc[i][j] = 0.f;

    const int arow = t >> 1;
    const int ac4  = (t & 1) * 4;
    const float* Ap = X + (long)(m0 + arow) * K + ac4;
    const float* Bp = W + (long)(n0 + arow) * K + ac4;

    for (int kt = 0; kt < K; kt += 8) {
        float4 a = *(const float4*)(Ap + kt);
        float4 b = *(const float4*)(Bp + kt);
        As[ac4 + 0][arow] = a.x; As[ac4 + 1][arow] = a.y;
        As[ac4 + 2][arow] = a.z; As[ac4 + 3][arow] = a.w;
        Bs[ac4 + 0][arow] = b.x; Bs[ac4 + 1][arow] = b.y;
        Bs[ac4 + 2][arow] = b.z; Bs[ac4 + 3][arow] = b.w;
        __syncthreads();
#pragma unroll
        for (int kk = 0; kk < 8; kk++) {
            float ar[8], br[8];
            *(float4*)(ar)     = *(const float4*)&As[kk][ty * 8];
            *(float4*)(ar + 4) = *(const float4*)&As[kk][ty * 8 + 4];
            *(float4*)(br)     = *(const float4*)&Bs[kk][tx * 8];
            *(float4*)(br + 4) = *(const float4*)&Bs[kk][tx * 8 + 4];
#pragma unroll
            for (int i = 0; i < 8; i++)
#pragma unroll
                for (int j = 0; j < 8; j++) acc[i][j] += ar[i] * br[j];
        }
        __syncthreads();
    }

    // Epilogue: scatter to [b][n][s][d]
#pragma unroll
    for (int j = 0; j < 8; j++) {
        int jg    = n0 + tx * 8 + j;
        float bj  = bias[jg];
        int which = jg >> 10;          // 0=q 1=k 2=v
        int hh    = jg & 1023;
        int hn    = hh >> 6;
        int d     = hh & 63;
        float* dst = (which == 0) ? g_q : ((which == 1) ? g_k : g_v);
        float scale = (which == 0) ? 0.125f : 1.0f;   // D^-0.5 folded into Q
#pragma unroll
        for (int i = 0; i < 8; i++) {
            int mg = m0 + ty * 8 + i;
            int bb = mg >> 11;
            int s  = mg & 2047;
            dst[(((bb * NH + hn) * SS) + s) * DD + d] = (acc[i][j] + bj) * scale;
        }
    }
}

// ---------------------------------------------------------------------------
// Kernel 2: causal flash attention. One block = one (b,n, 64-row q-tile).
// BK=32 k-tiles, online softmax, 16x16 thread grid, 4x2 S-frag / 4x4 O-frag.
// ---------------------------------------------------------------------------
__global__ __launch_bounds__(256) void flash_attn()
{
    __shared__ float Qs[64][68];  // [d][r]
    __shared__ float Ks[64][36];  // [d][c]
    __shared__ float Vs[32][64];  // [kc][d]
    __shared__ float Ps[32][68];  // [kc][r]

    const int t  = threadIdx.x;
    const int tx = t & 15;
    const int ty = t >> 4;
    const int bn = blockIdx.y;          // b*16+n
    const int q0 = blockIdx.x * 64;

    const float* Qp = g_q + (long)bn * SS * DD;
    const float* Kp = g_k + (long)bn * SS * DD;
    const float* Vp = g_v + (long)bn * SS * DD;

    // Load Q tile transposed -> Qs[d][r]
#pragma unroll
    for (int p = 0; p < 4; p++) {
        int idx = t + p * 256;          // 1024 float4 slots over 64x64
        int r   = idx >> 4;
        int d4  = (idx & 15) * 4;
        float4 qv = *(const float4*)(Qp + (q0 + r) * DD + d4);
        Qs[d4 + 0][r] = qv.x; Qs[d4 + 1][r] = qv.y;
        Qs[d4 + 2][r] = qv.z; Qs[d4 + 3][r] = qv.w;
    }

    float o[4][4];
    float mi[4], li[4];
#pragma unroll
    for (int i = 0; i < 4; i++) {
        mi[i] = -1e30f; li[i] = 0.f;
#pragma unroll
        for (int j = 0; j < 4; j++) o[i][j] = 0.f;
    }

    const int r0 = ty * 4;
    const int c0 = tx * 2;
    const int d0 = tx * 4;
    const int nkt = (q0 + 64) >> 5;     // causal: only tiles up to the diagonal

    for (int kt = 0; kt < nkt; kt++) {
        const int k0 = kt * 32;
        __syncthreads();                // protect Ks/Vs/Ps from previous iter
        // Load K (transposed) and V tiles: 32x64 each = 512 float4 each
#pragma unroll
        for (int p = 0; p < 2; p++) {
            int id = t + p * 256;
            int kc = id >> 4;
            int d4 = (id & 15) * 4;
            float4 kv = *(const float4*)(Kp + (k0 + kc) * DD + d4);
            Ks[d4 + 0][kc] = kv.x; Ks[d4 + 1][kc] = kv.y;
            Ks[d4 + 2][kc] = kv.z; Ks[d4 + 3][kc] = kv.w;
            float4 vv = *(const float4*)(Vp + (k0 + kc) * DD + d4);
            *(float4*)&Vs[kc][d4] = vv;
        }
        __syncthreads();

        // S = Q K^T  (Q already carries the 1/sqrt(D) scale)
        float s[4][2];
#pragma unroll
        for (int i = 0; i < 4; i++) { s[i][0] = 0.f; s[i][1] = 0.f; }
#pragma unroll
        for (int d = 0; d < 64; d++) {
            float4 qv = *(const float4*)&Qs[d][r0];
            float2 kv = *(const float2*)&Ks[d][c0];
            s[0][0] += qv.x * kv.x; s[0][1] += qv.x * kv.y;
            s[1][0] += qv.y * kv.x; s[1][1] += qv.y * kv.y;
            s[2][0] += qv.z * kv.x; s[2][1] += qv.z * kv.y;
            s[3][0] += qv.w * kv.x; s[3][1] += qv.w * kv.y;
        }

        // causal mask + online softmax per owned row
#pragma unroll
        for (int i = 0; i < 4; i++) {
            int qg = q0 + r0 + i;
            if (k0 + c0 + 0 > qg) s[i][0] = -1e30f;
            if (k0 + c0 + 1 > qg) s[i][1] = -1e30f;
            float rm = fmaxf(s[i][0], s[i][1]);
#pragma unroll
            for (int off = 8; off; off >>= 1)
                rm = fmaxf(rm, __shfl_xor_sync(0xffffffffu, rm, off));
            float mn = fmaxf(mi[i], rm);
            float alpha = __expf(mi[i] - mn);
            mi[i] = mn;
            float p0 = __expf(s[i][0] - mn);
            float p1 = __expf(s[i][1] - mn);
            float rs = p0 + p1;
#pragma unroll
            for (int off = 8; off; off >>= 1)
                rs += __shfl_xor_sync(0xffffffffu, rs, off);
            li[i] = li[i] * alpha + rs;
#pragma unroll
            for (int j = 0; j < 4; j++) o[i][j] *= alpha;
            Ps[c0 + 0][r0 + i] = p0;
            Ps[c0 + 1][r0 + i] = p1;
        }
        __syncthreads();

        // O += P @ V
#pragma unroll
        for (int kc = 0; kc < 32; kc++) {
            float4 pv = *(const float4*)&Ps[kc][r0];
            float4 vv = *(const float4*)&Vs[kc][d0];
            o[0][0] += pv.x * vv.x; o[0][1] += pv.x * vv.y; o[0][2] += pv.x * vv.z; o[0][3] += pv.x * vv.w;
            o[1][0] += pv.y * vv.x; o[1][1] += pv.y * vv.y; o[1][2] += pv.y * vv.z; o[1][3] += pv.y * vv.w;
            o[2][0] += pv.z * vv.x; o[2][1] += pv.z * vv.y; o[2][2] += pv.z * vv.z; o[2][3] += pv.z * vv.w;
            o[3][0] += pv.w * vv.x; o[3][1] += pv.w * vv.y; o[3][2] += pv.w * vv.z; o[3][3] += pv.w * vv.w;
        }
    }

    // finalize: divide by l, write to g_o[b*s][n*64+d]
    const int b  = bn >> 4;
    const int hn = bn & 15;
#pragma unroll
    for (int i = 0; i < 4; i++) {
        float inv = 1.0f / li[i];
        float4 ov = make_float4(o[i][0] * inv, o[i][1] * inv, o[i][2] * inv, o[i][3] * inv);
        int sg = q0 + r0 + i;
        *(float4*)&g_o[((long)(b * SS + sg)) * HH + hn * DD + d0] = ov;
    }
}

// ---------------------------------------------------------------------------
// Kernel 3: out projection. Y[M,H] = O[M,H] @ Wout[H,H]^T + b_out
// ---------------------------------------------------------------------------
__global__ __launch_bounds__(256) void gemm_out(const float* __restrict__ W,
                                                const float* __restrict__ bias,
                                                float* __restrict__ Y)
{
    __shared__ float As[8][128];
    __shared__ float Bs[8][128];

    const int t  = threadIdx.x;
    const int tx = t & 15;
    const int ty = t >> 4;
    const int m0 = blockIdx.y * 128;
    const int n0 = blockIdx.x * 128;
    const int K  = HH;

    float acc[8][8];
#pragma unroll
    for (int i = 0; i < 8; i++)
#pragma unroll
        for (int j = 0; j < 8; j++) acc[i][j] = 0.f;

    const int arow = t >> 1;
    const int ac4  = (t & 1) * 4;
    const float* Ap = g_o + (long)(m0 + arow) * K + ac4;
    const float* Bp = W   + (long)(n0 + arow) * K + ac4;

    for (int kt = 0; kt < K; kt += 8) {
        float4 a = *(const float4*)(Ap + kt);
        float4 b = *(const float4*)(Bp + kt);
        As[ac4 + 0][arow] = a.x; As[ac4 + 1][arow] = a.y;
        As[ac4 + 2][arow] = a.z; As[ac4 + 3][arow] = a.w;
        Bs[ac4 + 0][arow] = b.x; Bs[ac4 + 1][arow] = b.y;
        Bs[ac4 + 2][arow] = b.z; Bs[ac4 + 3][arow] = b.w;
        __syncthreads();
#pragma unroll
        for (int kk = 0; kk < 8; kk++) {
            float ar[8], br[8];
            *(float4*)(ar)     = *(const float4*)&As[kk][ty * 8];
            *(float4*)(ar + 4) = *(const float4*)&As[kk][ty * 8 + 4];
            *(float4*)(br)     = *(const float4*)&Bs[kk][tx * 8];
            *(float4*)(br + 4) = *(const float4*)&Bs[kk][tx * 8 + 4];
#pragma unroll
            for (int i = 0; i < 8; i++)
#pragma unroll
                for (int j = 0; j < 8; j++) acc[i][j] += ar[i] * br[j];
        }
        __syncthreads();
    }

#pragma unroll
    for (int j = 0; j < 8; j++) {
        int jg   = n0 + tx * 8 + j;
        float bj = bias[jg];
#pragma unroll
        for (int i = 0; i < 8; i++) {
            int mg = m0 + ty * 8 + i;
            Y[(long)mg * HH + jg] = acc[i][j] + bj;
        }
    }
}

// ---------------------------------------------------------------------------
extern "C" void kernel_launch(void* const* d_in, const int* in_sizes, int n_in,
                              void* d_out, int out_size)
{
    const float* hs    = (const float*)d_in[0];  // [B,S,H]
    const float* w_in  = (const float*)d_in[1];  // [3H,H]
    const float* b_in  = (const float*)d_in[2];  // [3H]
    const float* w_out = (const float*)d_in[3];  // [H,H]
    const float* b_out = (const float*)d_in[4];  // [H]
    float* out = (float*)d_out;                  // [B,S,H]

    (void)in_sizes; (void)n_in; (void)out_size;

    gemm_qkv <<<dim3(K3H / 128, MM / 128), 256>>>(hs, w_in, b_in);
    flash_attn<<<dim3(SS / 64, BB * NH), 256>>>();
    gemm_out <<<dim3(HH / 128, MM / 128), 256>>>(w_out, b_out, out);
}

// round 5
// speedup vs baseline: 1.6960x; 1.6960x over previous
#include <cuda_runtime.h>
#include <cuda_bf16.h>
#include <cstdint>

// Problem dims
#define BB 2
#define SS 2048
#define HH 1024
#define NH 16
#define DD 64
#define MM (BB * SS)       // 4096 rows
#define K3H (3 * HH)       // 3072

// GEMM tiling
#define MT 128
#define NT 128
#define KC 16
#define NCHUNK (HH / KC)   // 64
#define LDS_PAD 20         // floats per row in SMEM (conflict-free fragment loads)

// Scratch (device globals; no allocation allowed)
__device__ float g_q[BB * NH * SS * DD];   // [b][n][s][d], pre-scaled by D^-0.5
__device__ float g_k[BB * NH * SS * DD];
__device__ float g_v[BB * NH * SS * DD];
__device__ float g_o[MM * HH];             // [b*s][h] with h = n*64 + d

__device__ __forceinline__ uint32_t f2tf32(float x) {
    uint32_t r;
    asm("cvt.rna.tf32.f32 %0, %1;" : "=r"(r) : "f"(x));
    return r;
}

__device__ __forceinline__ void mma_tf32(float* d, const uint32_t* a, const uint32_t* b) {
    asm volatile(
        "mma.sync.aligned.m16n8k8.row.col.f32.tf32.tf32.f32 "
        "{%0,%1,%2,%3}, {%4,%5,%6,%7}, {%8,%9}, {%0,%1,%2,%3};"
        : "+f"(d[0]), "+f"(d[1]), "+f"(d[2]), "+f"(d[3])
        : "r"(a[0]), "r"(a[1]), "r"(a[2]), "r"(a[3]), "r"(b[0]), "r"(b[1]));
}

// ---------------------------------------------------------------------------
// tf32 mma.sync GEMM: C[MT,NT] = A[m0:,1024] * W[n0:,1024]^T (both K-major)
// Static SMEM only (40KB) -> no opt-in needed.
// MODE 0: A = hs (kernel arg). QKV epilogue: scatter to g_q/g_k/g_v (+bias,
//         Q scaled 0.125).
// MODE 1: A = g_o (resolved IN DEVICE CODE -- a __device__ global must never
//         be passed as a host-side kernel argument). Y = C + bias.
// ---------------------------------------------------------------------------
template <int MODE>
__global__ void __launch_bounds__(256)
gemm_mma(const float* __restrict__ A, const float* __restrict__ W,
         const float* __restrict__ bias, float* __restrict__ Y)
{
    __shared__ float Asm[2][MT][LDS_PAD];
    __shared__ float Bsm[2][NT][LDS_PAD];

    // Resolve A inside device code (g_o decays to a valid device pointer here)
    const float* Aptr = (MODE == 1) ? (const float*)g_o : A;

    const int t    = threadIdx.x;
    const int wid  = t >> 5;
    const int lane = t & 31;
    const int g    = lane >> 2;          // group id 0..7
    const int c    = lane & 3;           // thread-in-group 0..3
    const int wm   = (wid >> 2) * 64;    // warp m offset: 0 / 64
    const int wn   = (wid & 3) * 32;     // warp n offset: 0/32/64/96
    const int m0   = blockIdx.y * MT;
    const int n0   = blockIdx.x * NT;

    // global-load / SMEM-store mapping: row = t>>1 (0..127), 8-float half = (t&1)*8
    const int lrow = t >> 1;
    const int lk   = (t & 1) * 8;
    const float* Ag = Aptr + (long)(m0 + lrow) * HH + lk;
    const float* Bg = W    + (long)(n0 + lrow) * HH + lk;

    float acc[4][4][4];
#pragma unroll
    for (int mi = 0; mi < 4; mi++)
#pragma unroll
        for (int ni = 0; ni < 4; ni++)
#pragma unroll
            for (int k = 0; k < 4; k++) acc[mi][ni][k] = 0.f;

    float4 pa[2], pb[2];

    // prologue: chunk 0 -> stage 0
#pragma unroll
    for (int p = 0; p < 2; p++) {
        pa[p] = *(const float4*)(Ag + p * 4);
        pb[p] = *(const float4*)(Bg + p * 4);
    }
#pragma unroll
    for (int p = 0; p < 2; p++) {
        uint4 wa = make_uint4(f2tf32(pa[p].x), f2tf32(pa[p].y), f2tf32(pa[p].z), f2tf32(pa[p].w));
        uint4 wb = make_uint4(f2tf32(pb[p].x), f2tf32(pb[p].y), f2tf32(pb[p].z), f2tf32(pb[p].w));
        *(uint4*)&Asm[0][lrow][lk + p * 4] = wa;
        *(uint4*)&Bsm[0][lrow][lk + p * 4] = wb;
    }
    __syncthreads();

#pragma unroll 1
    for (int kt = 0; kt < NCHUNK; kt++) {
        // prefetch next chunk into registers
        if (kt + 1 < NCHUNK) {
            const float* Agn = Ag + (kt + 1) * KC;
            const float* Bgn = Bg + (kt + 1) * KC;
#pragma unroll
            for (int p = 0; p < 2; p++) {
                pa[p] = *(const float4*)(Agn + p * 4);
                pb[p] = *(const float4*)(Bgn + p * 4);
            }
        }

        // compute on stage kt&1
        {
            const int st = kt & 1;
#pragma unroll
            for (int ks = 0; ks < 2; ks++) {
                const int k0 = ks * 8 + c;
                uint32_t af[4][4], bf[4][2];
#pragma unroll
                for (int mi = 0; mi < 4; mi++) {
                    const float* pr = &Asm[st][wm + mi * 16 + g][k0];
                    af[mi][0] = __float_as_uint(pr[0]);
                    af[mi][1] = __float_as_uint(pr[8 * LDS_PAD]);
                    af[mi][2] = __float_as_uint(pr[4]);
                    af[mi][3] = __float_as_uint(pr[8 * LDS_PAD + 4]);
                }
#pragma unroll
                for (int ni = 0; ni < 4; ni++) {
                    const float* pc = &Bsm[st][wn + ni * 8 + g][k0];
                    bf[ni][0] = __float_as_uint(pc[0]);
                    bf[ni][1] = __float_as_uint(pc[4]);
                }
#pragma unroll
                for (int mi = 0; mi < 4; mi++)
#pragma unroll
                    for (int ni = 0; ni < 4; ni++)
                        mma_tf32(acc[mi][ni], af[mi], bf[ni]);
            }
        }

        // store prefetched chunk into the other stage
        if (kt + 1 < NCHUNK) {
            const int sn = (kt + 1) & 1;
#pragma unroll
            for (int p = 0; p < 2; p++) {
                uint4 wa = make_uint4(f2tf32(pa[p].x), f2tf32(pa[p].y), f2tf32(pa[p].z), f2tf32(pa[p].w));
                uint4 wb = make_uint4(f2tf32(pb[p].x), f2tf32(pb[p].y), f2tf32(pb[p].z), f2tf32(pb[p].w));
                *(uint4*)&Asm[sn][lrow][lk + p * 4] = wa;
                *(uint4*)&Bsm[sn][lrow][lk + p * 4] = wb;
            }
            __syncthreads();
        }
    }

    // Epilogue: write accumulators with bias (+ scatter for MODE 0)
#pragma unroll
    for (int ni = 0; ni < 4; ni++) {
        const int col = n0 + wn + ni * 8 + 2 * c;
        const float b0 = bias[col];
        const float b1 = bias[col + 1];
        float scale = 1.0f;
        float* dst0 = nullptr;
        int hn = 0, d = 0;
        if (MODE == 0) {
            const int which = col >> 10;
            hn = (col & 1023) >> 6;
            d  = col & 63;
            dst0 = (which == 0) ? g_q : ((which == 1) ? g_k : g_v);
            if (which == 0) scale = 0.125f;
        }
#pragma unroll
        for (int mi = 0; mi < 4; mi++) {
            const int r1 = m0 + wm + mi * 16 + g;
            const int r2 = r1 + 8;
            float2 v1 = make_float2((acc[mi][ni][0] + b0) * scale,
                                    (acc[mi][ni][1] + b1) * scale);
            float2 v2 = make_float2((acc[mi][ni][2] + b0) * scale,
                                    (acc[mi][ni][3] + b1) * scale);
            if (MODE == 0) {
                const int bb1 = r1 >> 11, s1 = r1 & 2047;
                const int bb2 = r2 >> 11, s2 = r2 & 2047;
                *(float2*)(dst0 + (((long)(bb1 * NH + hn) * SS) + s1) * DD + d) = v1;
                *(float2*)(dst0 + (((long)(bb2 * NH + hn) * SS) + s2) * DD + d) = v2;
            } else {
                *(float2*)(Y + (long)r1 * HH + col) = v1;
                *(float2*)(Y + (long)r2 * HH + col) = v2;
            }
        }
    }
}

// ---------------------------------------------------------------------------
// Kernel 2: causal flash attention (fp32 SIMT, unchanged / known-good)
// ---------------------------------------------------------------------------
__global__ __launch_bounds__(256) void flash_attn()
{
    __shared__ float Qs[64][68];  // [d][r]
    __shared__ float Ks[64][36];  // [d][c]
    __shared__ float Vs[32][64];  // [kc][d]
    __shared__ float Ps[32][68];  // [kc][r]

    const int t  = threadIdx.x;
    const int tx = t & 15;
    const int ty = t >> 4;
    const int bn = blockIdx.y;          // b*16+n
    const int q0 = blockIdx.x * 64;

    const float* Qp = g_q + (long)bn * SS * DD;
    const float* Kp = g_k + (long)bn * SS * DD;
    const float* Vp = g_v + (long)bn * SS * DD;

#pragma unroll
    for (int p = 0; p < 4; p++) {
        int idx = t + p * 256;
        int r   = idx >> 4;
        int d4  = (idx & 15) * 4;
        float4 qv = *(const float4*)(Qp + (q0 + r) * DD + d4);
        Qs[d4 + 0][r] = qv.x; Qs[d4 + 1][r] = qv.y;
        Qs[d4 + 2][r] = qv.z; Qs[d4 + 3][r] = qv.w;
    }

    float o[4][4];
    float mi[4], li[4];
#pragma unroll
    for (int i = 0; i < 4; i++) {
        mi[i] = -1e30f; li[i] = 0.f;
#pragma unroll
        for (int j = 0; j < 4; j++) o[i][j] = 0.f;
    }

    const int r0 = ty * 4;
    const int c0 = tx * 2;
    const int d0 = tx * 4;
    const int nkt = (q0 + 64) >> 5;

    for (int kt = 0; kt < nkt; kt++) {
        const int k0 = kt * 32;
        __syncthreads();
#pragma unroll
        for (int p = 0; p < 2; p++) {
            int id = t + p * 256;
            int kc = id >> 4;
            int d4 = (id & 15) * 4;
            float4 kv = *(const float4*)(Kp + (k0 + kc) * DD + d4);
            Ks[d4 + 0][kc] = kv.x; Ks[d4 + 1][kc] = kv.y;
            Ks[d4 + 2][kc] = kv.z; Ks[d4 + 3][kc] = kv.w;
            float4 vv = *(const float4*)(Vp + (k0 + kc) * DD + d4);
            *(float4*)&Vs[kc][d4] = vv;
        }
        __syncthreads();

        float s[4][2];
#pragma unroll
        for (int i = 0; i < 4; i++) { s[i][0] = 0.f; s[i][1] = 0.f; }
#pragma unroll
        for (int d = 0; d < 64; d++) {
            float4 qv = *(const float4*)&Qs[d][r0];
            float2 kv = *(const float2*)&Ks[d][c0];
            s[0][0] += qv.x * kv.x; s[0][1] += qv.x * kv.y;
            s[1][0] += qv.y * kv.x; s[1][1] += qv.y * kv.y;
            s[2][0] += qv.z * kv.x; s[2][1] += qv.z * kv.y;
            s[3][0] += qv.w * kv.x; s[3][1] += qv.w * kv.y;
        }

#pragma unroll
        for (int i = 0; i < 4; i++) {
            int qg = q0 + r0 + i;
            if (k0 + c0 + 0 > qg) s[i][0] = -1e30f;
            if (k0 + c0 + 1 > qg) s[i][1] = -1e30f;
            float rm = fmaxf(s[i][0], s[i][1]);
#pragma unroll
            for (int off = 8; off; off >>= 1)
                rm = fmaxf(rm, __shfl_xor_sync(0xffffffffu, rm, off));
            float mn = fmaxf(mi[i], rm);
            float alpha = __expf(mi[i] - mn);
            mi[i] = mn;
            float p0 = __expf(s[i][0] - mn);
            float p1 = __expf(s[i][1] - mn);
            float rs = p0 + p1;
#pragma unroll
            for (int off = 8; off; off >>= 1)
                rs += __shfl_xor_sync(0xffffffffu, rs, off);
            li[i] = li[i] * alpha + rs;
#pragma unroll
            for (int j = 0; j < 4; j++) o[i][j] *= alpha;
            Ps[c0 + 0][r0 + i] = p0;
            Ps[c0 + 1][r0 + i] = p1;
        }
        __syncthreads();

#pragma unroll
        for (int kc = 0; kc < 32; kc++) {
            float4 pv = *(const float4*)&Ps[kc][r0];
            float4 vv = *(const float4*)&Vs[kc][d0];
            o[0][0] += pv.x * vv.x; o[0][1] += pv.x * vv.y; o[0][2] += pv.x * vv.z; o[0][3] += pv.x * vv.w;
            o[1][0] += pv.y * vv.x; o[1][1] += pv.y * vv.y; o[1][2] += pv.y * vv.z; o[1][3] += pv.y * vv.w;
            o[2][0] += pv.z * vv.x; o[2][1] += pv.z * vv.y; o[2][2] += pv.z * vv.z; o[2][3] += pv.z * vv.w;
            o[3][0] += pv.w * vv.x; o[3][1] += pv.w * vv.y; o[3][2] += pv.w * vv.z; o[3][3] += pv.w * vv.w;
        }
    }

    const int b  = bn >> 4;
    const int hn = bn & 15;
#pragma unroll
    for (int i = 0; i < 4; i++) {
        float inv = 1.0f / li[i];
        float4 ov = make_float4(o[i][0] * inv, o[i][1] * inv, o[i][2] * inv, o[i][3] * inv);
        int sg = q0 + r0 + i;
        *(float4*)&g_o[((long)(b * SS + sg)) * HH + hn * DD + d0] = ov;
    }
}

// ---------------------------------------------------------------------------
extern "C" void kernel_launch(void* const* d_in, const int* in_sizes, int n_in,
                              void* d_out, int out_size)
{
    const float* hs    = (const float*)d_in[0];  // [B,S,H]
    const float* w_in  = (const float*)d_in[1];  // [3H,H]
    const float* b_in  = (const float*)d_in[2];  // [3H]
    const float* w_out = (const float*)d_in[3];  // [H,H]
    const float* b_out = (const float*)d_in[4];  // [H]
    float* out = (float*)d_out;                  // [B,S,H]

    (void)in_sizes; (void)n_in; (void)out_size;

    // NOTE: never pass __device__ globals (g_q/g_k/g_v/g_o) as host-side
    // kernel arguments -- they are resolved inside device code instead.
    gemm_mma<0><<<dim3(K3H / NT, MM / MT), 256>>>(hs, w_in, b_in, nullptr);
    flash_attn<<<dim3(SS / 64, BB * NH), 256>>>();
    gemm_mma<1><<<dim3(HH / NT, MM / MT), 256>>>(nullptr, w_out, b_out, out);
}

// round 6
// speedup vs baseline: 3.3053x; 1.9489x over previous
#include <cuda_runtime.h>
#include <cuda_bf16.h>
#include <cstdint>

// Problem dims
#define BB 2
#define SS 2048
#define HH 1024
#define NH 16
#define DD 64
#define MM (BB * SS)       // 4096 rows
#define K3H (3 * HH)       // 3072

// GEMM tiling
#define MT 128
#define NT 128
#define KC 16
#define NCHUNK (HH / KC)   // 64
#define LDS_PAD 20

// Scratch (device globals; no allocation allowed)
__device__ float g_q[BB * NH * SS * DD];   // [b][n][s][d], pre-scaled by D^-0.5
__device__ float g_k[BB * NH * SS * DD];
__device__ float g_v[BB * NH * SS * DD];
__device__ float g_o[MM * HH];             // [b*s][h] with h = n*64 + d

__device__ __forceinline__ uint32_t f2tf32(float x) {
    uint32_t r;
    asm("cvt.rna.tf32.f32 %0, %1;" : "=r"(r) : "f"(x));
    return r;
}
__device__ __forceinline__ float tf32f(float x) { return __uint_as_float(f2tf32(x)); }

__device__ __forceinline__ void mma_tf32(float* d, const uint32_t* a, const uint32_t* b) {
    asm volatile(
        "mma.sync.aligned.m16n8k8.row.col.f32.tf32.tf32.f32 "
        "{%0,%1,%2,%3}, {%4,%5,%6,%7}, {%8,%9}, {%0,%1,%2,%3};"
        : "+f"(d[0]), "+f"(d[1]), "+f"(d[2]), "+f"(d[3])
        : "r"(a[0]), "r"(a[1]), "r"(a[2]), "r"(a[3]), "r"(b[0]), "r"(b[1]));
}

// ---------------------------------------------------------------------------
// tf32 mma.sync GEMM (unchanged from R5, known good)
// ---------------------------------------------------------------------------
template <int MODE>
__global__ void __launch_bounds__(256)
gemm_mma(const float* __restrict__ A, const float* __restrict__ W,
         const float* __restrict__ bias, float* __restrict__ Y)
{
    __shared__ float Asm[2][MT][LDS_PAD];
    __shared__ float Bsm[2][NT][LDS_PAD];

    const float* Aptr = (MODE == 1) ? (const float*)g_o : A;

    const int t    = threadIdx.x;
    const int wid  = t >> 5;
    const int lane = t & 31;
    const int g    = lane >> 2;
    const int c    = lane & 3;
    const int wm   = (wid >> 2) * 64;
    const int wn   = (wid & 3) * 32;
    const int m0   = blockIdx.y * MT;
    const int n0   = blockIdx.x * NT;

    const int lrow = t >> 1;
    const int lk   = (t & 1) * 8;
    const float* Ag = Aptr + (long)(m0 + lrow) * HH + lk;
    const float* Bg = W    + (long)(n0 + lrow) * HH + lk;

    float acc[4][4][4];
#pragma unroll
    for (int mi = 0; mi < 4; mi++)
#pragma unroll
        for (int ni = 0; ni < 4; ni++)
#pragma unroll
            for (int k = 0; k < 4; k++) acc[mi][ni][k] = 0.f;

    float4 pa[2], pb[2];
#pragma unroll
    for (int p = 0; p < 2; p++) {
        pa[p] = *(const float4*)(Ag + p * 4);
        pb[p] = *(const float4*)(Bg + p * 4);
    }
#pragma unroll
    for (int p = 0; p < 2; p++) {
        uint4 wa = make_uint4(f2tf32(pa[p].x), f2tf32(pa[p].y), f2tf32(pa[p].z), f2tf32(pa[p].w));
        uint4 wb = make_uint4(f2tf32(pb[p].x), f2tf32(pb[p].y), f2tf32(pb[p].z), f2tf32(pb[p].w));
        *(uint4*)&Asm[0][lrow][lk + p * 4] = wa;
        *(uint4*)&Bsm[0][lrow][lk + p * 4] = wb;
    }
    __syncthreads();

#pragma unroll 1
    for (int kt = 0; kt < NCHUNK; kt++) {
        if (kt + 1 < NCHUNK) {
            const float* Agn = Ag + (kt + 1) * KC;
            const float* Bgn = Bg + (kt + 1) * KC;
#pragma unroll
            for (int p = 0; p < 2; p++) {
                pa[p] = *(const float4*)(Agn + p * 4);
                pb[p] = *(const float4*)(Bgn + p * 4);
            }
        }
        {
            const int st = kt & 1;
#pragma unroll
            for (int ks = 0; ks < 2; ks++) {
                const int k0 = ks * 8 + c;
                uint32_t af[4][4], bf[4][2];
#pragma unroll
                for (int mi = 0; mi < 4; mi++) {
                    const float* pr = &Asm[st][wm + mi * 16 + g][k0];
                    af[mi][0] = __float_as_uint(pr[0]);
                    af[mi][1] = __float_as_uint(pr[8 * LDS_PAD]);
                    af[mi][2] = __float_as_uint(pr[4]);
                    af[mi][3] = __float_as_uint(pr[8 * LDS_PAD + 4]);
                }
#pragma unroll
                for (int ni = 0; ni < 4; ni++) {
                    const float* pc = &Bsm[st][wn + ni * 8 + g][k0];
                    bf[ni][0] = __float_as_uint(pc[0]);
                    bf[ni][1] = __float_as_uint(pc[4]);
                }
#pragma unroll
                for (int mi = 0; mi < 4; mi++)
#pragma unroll
                    for (int ni = 0; ni < 4; ni++)
                        mma_tf32(acc[mi][ni], af[mi], bf[ni]);
            }
        }
        if (kt + 1 < NCHUNK) {
            const int sn = (kt + 1) & 1;
#pragma unroll
            for (int p = 0; p < 2; p++) {
                uint4 wa = make_uint4(f2tf32(pa[p].x), f2tf32(pa[p].y), f2tf32(pa[p].z), f2tf32(pa[p].w));
                uint4 wb = make_uint4(f2tf32(pb[p].x), f2tf32(pb[p].y), f2tf32(pb[p].z), f2tf32(pb[p].w));
                *(uint4*)&Asm[sn][lrow][lk + p * 4] = wa;
                *(uint4*)&Bsm[sn][lrow][lk + p * 4] = wb;
            }
            __syncthreads();
        }
    }

#pragma unroll
    for (int ni = 0; ni < 4; ni++) {
        const int col = n0 + wn + ni * 8 + 2 * c;
        const float b0 = bias[col];
        const float b1 = bias[col + 1];
        float scale = 1.0f;
        float* dst0 = nullptr;
        int hn = 0, d = 0;
        if (MODE == 0) {
            const int which = col >> 10;
            hn = (col & 1023) >> 6;
            d  = col & 63;
            dst0 = (which == 0) ? g_q : ((which == 1) ? g_k : g_v);
            if (which == 0) scale = 0.125f;
        }
#pragma unroll
        for (int mi = 0; mi < 4; mi++) {
            const int r1 = m0 + wm + mi * 16 + g;
            const int r2 = r1 + 8;
            float2 v1 = make_float2((acc[mi][ni][0] + b0) * scale,
                                    (acc[mi][ni][1] + b1) * scale);
            float2 v2 = make_float2((acc[mi][ni][2] + b0) * scale,
                                    (acc[mi][ni][3] + b1) * scale);
            if (MODE == 0) {
                const int bb1 = r1 >> 11, s1 = r1 & 2047;
                const int bb2 = r2 >> 11, s2 = r2 & 2047;
                *(float2*)(dst0 + (((long)(bb1 * NH + hn) * SS) + s1) * DD + d) = v1;
                *(float2*)(dst0 + (((long)(bb2 * NH + hn) * SS) + s2) * DD + d) = v2;
            } else {
                *(float2*)(Y + (long)r1 * HH + col) = v1;
                *(float2*)(Y + (long)r2 * HH + col) = v2;
            }
        }
    }
}

// ---------------------------------------------------------------------------
// Kernel 2: causal flash attention on tensor cores (tf32 mma.sync).
// BQ=128 rows/CTA, BK=32 cols/iter, 8 warps, each warp owns 16 rows.
// Q fragments register-resident; P staged through warp-private SMEM strip.
// ---------------------------------------------------------------------------
__global__ __launch_bounds__(256) void flash_attn_mma()
{
    __shared__ float Ks[32][68];    // [kc][d]   QK B-frag LDS conflict-free
    __shared__ float Vs[32][72];    // [kc][d]   PV B-frag LDS conflict-free
    __shared__ float Ps[128][36];   // [qrow][kc] PV A-frag, warp-private rows

    const int t    = threadIdx.x;
    const int wid  = t >> 5;
    const int lane = t & 31;
    const int g    = lane >> 2;
    const int c    = lane & 3;
    const int bn   = blockIdx.y;        // b*16+n
    const int q0   = blockIdx.x * 128;
    const int wr   = wid * 16;          // warp row base within tile

    const float* Qp = g_q + (long)bn * SS * DD;
    const float* Kp = g_k + (long)bn * SS * DD;
    const float* Vp = g_v + (long)bn * SS * DD;

    // Q fragments (tf32), loaded once: rows q0+wr+g / +8, k = d
    uint32_t Qf[8][4];
    {
        const float* qr0 = Qp + (long)(q0 + wr + g) * DD;
        const float* qr1 = qr0 + 8 * DD;
#pragma unroll
        for (int kc = 0; kc < 8; kc++) {
            Qf[kc][0] = f2tf32(qr0[kc * 8 + c]);
            Qf[kc][1] = f2tf32(qr1[kc * 8 + c]);
            Qf[kc][2] = f2tf32(qr0[kc * 8 + c + 4]);
            Qf[kc][3] = f2tf32(qr1[kc * 8 + c + 4]);
        }
    }

    float O[8][4];                  // [dn][frag] over d=64
#pragma unroll
    for (int dn = 0; dn < 8; dn++)
#pragma unroll
        for (int k = 0; k < 4; k++) O[dn][k] = 0.f;
    float m0v = -1e30f, m1v = -1e30f, l0 = 0.f, l1 = 0.f;

    const int r0g = q0 + wr + g;
    const int r1g = r0g + 8;
    const int nkt = (q0 + 128) >> 5;    // causal: tiles up to the diagonal

    for (int kt = 0; kt < nkt; kt++) {
        const int k0 = kt * 32;
        __syncthreads();                // all warps done reading Ks/Vs
        // load K,V tiles (tf32-rounded): 32x64 each
#pragma unroll
        for (int p = 0; p < 2; p++) {
            int slot = t + p * 256;
            int row  = slot >> 4;
            int c4   = (slot & 15) * 4;
            float4 kv = *(const float4*)(Kp + (long)(k0 + row) * DD + c4);
            Ks[row][c4 + 0] = tf32f(kv.x); Ks[row][c4 + 1] = tf32f(kv.y);
            Ks[row][c4 + 2] = tf32f(kv.z); Ks[row][c4 + 3] = tf32f(kv.w);
            float4 vv = *(const float4*)(Vp + (long)(k0 + row) * DD + c4);
            Vs[row][c4 + 0] = tf32f(vv.x); Vs[row][c4 + 1] = tf32f(vv.y);
            Vs[row][c4 + 2] = tf32f(vv.z); Vs[row][c4 + 3] = tf32f(vv.w);
        }
        __syncthreads();

        // S = Q K^T  (Q carries the 1/sqrt(D) scale)
        float S[4][4];
#pragma unroll
        for (int ni = 0; ni < 4; ni++)
#pragma unroll
            for (int k = 0; k < 4; k++) S[ni][k] = 0.f;
#pragma unroll
        for (int kc = 0; kc < 8; kc++) {
#pragma unroll
            for (int ni = 0; ni < 4; ni++) {
                uint32_t bf[2];
                bf[0] = __float_as_uint(Ks[ni * 8 + g][kc * 8 + c]);
                bf[1] = __float_as_uint(Ks[ni * 8 + g][kc * 8 + c + 4]);
                mma_tf32(S[ni], Qf[kc], bf);
            }
        }

        // causal mask + row max
        float mx0 = m0v, mx1 = m1v;
#pragma unroll
        for (int ni = 0; ni < 4; ni++) {
            const int col0 = k0 + ni * 8 + 2 * c;
            const int col1 = col0 + 1;
            if (col0 > r0g) S[ni][0] = -1e30f;
            if (col1 > r0g) S[ni][1] = -1e30f;
            if (col0 > r1g) S[ni][2] = -1e30f;
            if (col1 > r1g) S[ni][3] = -1e30f;
            mx0 = fmaxf(mx0, fmaxf(S[ni][0], S[ni][1]));
            mx1 = fmaxf(mx1, fmaxf(S[ni][2], S[ni][3]));
        }
        mx0 = fmaxf(mx0, __shfl_xor_sync(0xffffffffu, mx0, 1));
        mx0 = fmaxf(mx0, __shfl_xor_sync(0xffffffffu, mx0, 2));
        mx1 = fmaxf(mx1, __shfl_xor_sync(0xffffffffu, mx1, 1));
        mx1 = fmaxf(mx1, __shfl_xor_sync(0xffffffffu, mx1, 2));

        const float a0 = __expf(m0v - mx0);
        const float a1 = __expf(m1v - mx1);
        m0v = mx0; m1v = mx1;

        float rs0 = 0.f, rs1 = 0.f;
#pragma unroll
        for (int ni = 0; ni < 4; ni++) {
            float p00 = __expf(S[ni][0] - mx0);
            float p01 = __expf(S[ni][1] - mx0);
            float p10 = __expf(S[ni][2] - mx1);
            float p11 = __expf(S[ni][3] - mx1);
            rs0 += p00 + p01; rs1 += p10 + p11;
            *(float2*)&Ps[wr + g][ni * 8 + 2 * c]     = make_float2(tf32f(p00), tf32f(p01));
            *(float2*)&Ps[wr + g + 8][ni * 8 + 2 * c] = make_float2(tf32f(p10), tf32f(p11));
        }
        rs0 += __shfl_xor_sync(0xffffffffu, rs0, 1);
        rs0 += __shfl_xor_sync(0xffffffffu, rs0, 2);
        rs1 += __shfl_xor_sync(0xffffffffu, rs1, 1);
        rs1 += __shfl_xor_sync(0xffffffffu, rs1, 2);
        l0 = l0 * a0 + rs0;
        l1 = l1 * a1 + rs1;

#pragma unroll
        for (int dn = 0; dn < 8; dn++) {
            O[dn][0] *= a0; O[dn][1] *= a0;
            O[dn][2] *= a1; O[dn][3] *= a1;
        }
        __syncwarp();   // order Ps stores (other lanes) before A-frag loads

        // O += P @ V
#pragma unroll
        for (int j = 0; j < 4; j++) {
            uint32_t Af[4];
            Af[0] = __float_as_uint(Ps[wr + g][j * 8 + c]);
            Af[1] = __float_as_uint(Ps[wr + g + 8][j * 8 + c]);
            Af[2] = __float_as_uint(Ps[wr + g][j * 8 + c + 4]);
            Af[3] = __float_as_uint(Ps[wr + g + 8][j * 8 + c + 4]);
#pragma unroll
            for (int dn = 0; dn < 8; dn++) {
                uint32_t bf[2];
                bf[0] = __float_as_uint(Vs[j * 8 + c][dn * 8 + g]);
                bf[1] = __float_as_uint(Vs[j * 8 + c + 4][dn * 8 + g]);
                mma_tf32(O[dn], Af, bf);
            }
        }
    }

    // epilogue: O /= l, write g_o[b*s][hn*64+d]
    const float inv0 = 1.0f / l0;
    const float inv1 = 1.0f / l1;
    const int b  = bn >> 4;
    const int hn = bn & 15;
    float* orow0 = g_o + (long)(b * SS + r0g) * HH + hn * DD;
    float* orow1 = orow0 + 8 * HH;
#pragma unroll
    for (int dn = 0; dn < 8; dn++) {
        *(float2*)(orow0 + dn * 8 + 2 * c) = make_float2(O[dn][0] * inv0, O[dn][1] * inv0);
        *(float2*)(orow1 + dn * 8 + 2 * c) = make_float2(O[dn][2] * inv1, O[dn][3] * inv1);
    }
}

// ---------------------------------------------------------------------------
extern "C" void kernel_launch(void* const* d_in, const int* in_sizes, int n_in,
                              void* d_out, int out_size)
{
    const float* hs    = (const float*)d_in[0];  // [B,S,H]
    const float* w_in  = (const float*)d_in[1];  // [3H,H]
    const float* b_in  = (const float*)d_in[2];  // [3H]
    const float* w_out = (const float*)d_in[3];  // [H,H]
    const float* b_out = (const float*)d_in[4];  // [H]
    float* out = (float*)d_out;                  // [B,S,H]

    (void)in_sizes; (void)n_in; (void)out_size;

    gemm_mma<0><<<dim3(K3H / NT, MM / MT), 256>>>(hs, w_in, b_in, nullptr);
    flash_attn_mma<<<dim3(SS / 128, BB * NH), 256>>>();
    gemm_mma<1><<<dim3(HH / NT, MM / MT), 256>>>(nullptr, w_out, b_out, out);
}

// round 7
// speedup vs baseline: 3.7647x; 1.1390x over previous
#include <cuda_runtime.h>
#include <cuda_bf16.h>
#include <cstdint>

// Problem dims
#define BB 2
#define SS 2048
#define HH 1024
#define NH 16
#define DD 64
#define MM (BB * SS)       // 4096 rows
#define K3H (3 * HH)       // 3072

// GEMM tiling
#define MT 128
#define NT 128
#define KC 16
#define NCHUNK (HH / KC)   // 64
#define LDS_PAD 20         // stride mod 32 == 4*k -> LDSM conflict-free

// Scratch (device globals; no allocation allowed)
__device__ float g_q[BB * NH * SS * DD];   // [b][n][s][d], pre-scaled by D^-0.5
__device__ float g_k[BB * NH * SS * DD];   // [b][n][s][d]
__device__ float g_v[BB * NH * DD * SS];   // [b][n][d][s]  (TRANSPOSED for PV ldmatrix)
__device__ float g_o[MM * HH];             // [b*s][h] with h = n*64 + d

__device__ __forceinline__ uint32_t f2tf32(float x) {
    uint32_t r;
    asm("cvt.rna.tf32.f32 %0, %1;" : "=r"(r) : "f"(x));
    return r;
}
__device__ __forceinline__ float tf32f(float x) { return __uint_as_float(f2tf32(x)); }

__device__ __forceinline__ void mma_tf32(float* d, const uint32_t* a, const uint32_t* b) {
    asm volatile(
        "mma.sync.aligned.m16n8k8.row.col.f32.tf32.tf32.f32 "
        "{%0,%1,%2,%3}, {%4,%5,%6,%7}, {%8,%9}, {%0,%1,%2,%3};"
        : "+f"(d[0]), "+f"(d[1]), "+f"(d[2]), "+f"(d[3])
        : "r"(a[0]), "r"(a[1]), "r"(a[2]), "r"(a[3]), "r"(b[0]), "r"(b[1]));
}

// ldmatrix x4 (b16 view): for tf32, an 8x4-tf32 tile seen as 8x8-b16 yields
// exactly the mma fragment distribution (thread i -> row i/4, col i%4).
__device__ __forceinline__ void ldsm4(uint32_t* r, const void* p) {
    uint32_t a = (uint32_t)__cvta_generic_to_shared(p);
    asm volatile("ldmatrix.sync.aligned.m8n8.x4.shared.b16 {%0,%1,%2,%3}, [%4];"
                 : "=r"(r[0]), "=r"(r[1]), "=r"(r[2]), "=r"(r[3]) : "r"(a));
}

// ---------------------------------------------------------------------------
// tf32 mma.sync GEMM with ldmatrix fragment loads.
// MODE 0: A = hs arg; scatter epilogue to g_q/g_k (s-major) and g_v (d-major).
// MODE 1: A = g_o (device-resolved); Y = C + bias.
// ---------------------------------------------------------------------------
template <int MODE>
__global__ void __launch_bounds__(256)
gemm_mma(const float* __restrict__ A, const float* __restrict__ W,
         const float* __restrict__ bias, float* __restrict__ Y)
{
    __shared__ float Asm[2][MT][LDS_PAD];
    __shared__ float Bsm[2][NT][LDS_PAD];

    const float* Aptr = (MODE == 1) ? (const float*)g_o : A;

    const int t    = threadIdx.x;
    const int wid  = t >> 5;
    const int lane = t & 31;
    const int g    = lane >> 2;
    const int c    = lane & 3;
    const int wm   = (wid >> 2) * 64;
    const int wn   = (wid & 3) * 32;
    const int m0   = blockIdx.y * MT;
    const int n0   = blockIdx.x * NT;

    // LDSM per-thread row/col offsets
    const int a_row = ((lane >> 3) & 1) * 8 + (lane & 7);
    const int a_kof = (lane >> 4) * 4;
    const int b_row = ((lane >> 4) & 1) * 8 + (lane & 7);
    const int b_kof = ((lane >> 3) & 1) * 4;

    const int lrow = t >> 1;
    const int lk   = (t & 1) * 8;
    const float* Ag = Aptr + (long)(m0 + lrow) * HH + lk;
    const float* Bg = W    + (long)(n0 + lrow) * HH + lk;

    float acc[4][4][4];
#pragma unroll
    for (int mi = 0; mi < 4; mi++)
#pragma unroll
        for (int ni = 0; ni < 4; ni++)
#pragma unroll
            for (int k = 0; k < 4; k++) acc[mi][ni][k] = 0.f;

    float4 pa[2], pb[2];
#pragma unroll
    for (int p = 0; p < 2; p++) {
        pa[p] = *(const float4*)(Ag + p * 4);
        pb[p] = *(const float4*)(Bg + p * 4);
    }
#pragma unroll
    for (int p = 0; p < 2; p++) {
        uint4 wa = make_uint4(f2tf32(pa[p].x), f2tf32(pa[p].y), f2tf32(pa[p].z), f2tf32(pa[p].w));
        uint4 wb = make_uint4(f2tf32(pb[p].x), f2tf32(pb[p].y), f2tf32(pb[p].z), f2tf32(pb[p].w));
        *(uint4*)&Asm[0][lrow][lk + p * 4] = wa;
        *(uint4*)&Bsm[0][lrow][lk + p * 4] = wb;
    }
    __syncthreads();

#pragma unroll 1
    for (int kt = 0; kt < NCHUNK; kt++) {
        if (kt + 1 < NCHUNK) {
            const float* Agn = Ag + (kt + 1) * KC;
            const float* Bgn = Bg + (kt + 1) * KC;
#pragma unroll
            for (int p = 0; p < 2; p++) {
                pa[p] = *(const float4*)(Agn + p * 4);
                pb[p] = *(const float4*)(Bgn + p * 4);
            }
        }
        {
            const int st = kt & 1;
#pragma unroll
            for (int ks = 0; ks < 2; ks++) {
                const int k0 = ks * 8;
                uint32_t af[4][4], bfp[2][4];
#pragma unroll
                for (int mi = 0; mi < 4; mi++)
                    ldsm4(af[mi], &Asm[st][wm + mi * 16 + a_row][k0 + a_kof]);
                ldsm4(bfp[0], &Bsm[st][wn + b_row][k0 + b_kof]);        // ni 0,1
                ldsm4(bfp[1], &Bsm[st][wn + 16 + b_row][k0 + b_kof]);   // ni 2,3
#pragma unroll
                for (int mi = 0; mi < 4; mi++) {
                    mma_tf32(acc[mi][0], af[mi], &bfp[0][0]);
                    mma_tf32(acc[mi][1], af[mi], &bfp[0][2]);
                    mma_tf32(acc[mi][2], af[mi], &bfp[1][0]);
                    mma_tf32(acc[mi][3], af[mi], &bfp[1][2]);
                }
            }
        }
        if (kt + 1 < NCHUNK) {
            const int sn = (kt + 1) & 1;
#pragma unroll
            for (int p = 0; p < 2; p++) {
                uint4 wa = make_uint4(f2tf32(pa[p].x), f2tf32(pa[p].y), f2tf32(pa[p].z), f2tf32(pa[p].w));
                uint4 wb = make_uint4(f2tf32(pb[p].x), f2tf32(pb[p].y), f2tf32(pb[p].z), f2tf32(pb[p].w));
                *(uint4*)&Asm[sn][lrow][lk + p * 4] = wa;
                *(uint4*)&Bsm[sn][lrow][lk + p * 4] = wb;
            }
            __syncthreads();
        }
    }

    // Epilogue
#pragma unroll
    for (int ni = 0; ni < 4; ni++) {
        const int col = n0 + wn + ni * 8 + 2 * c;
        const float b0 = bias[col];
        const float b1 = bias[col + 1];
#pragma unroll
        for (int mi = 0; mi < 4; mi++) {
            const int r1 = m0 + wm + mi * 16 + g;
            const int r2 = r1 + 8;
            if (MODE == 0) {
                const int which = col >> 10;
                const int hn    = (col & 1023) >> 6;
                const int d     = col & 63;
                const float scale = (which == 0) ? 0.125f : 1.0f;
                const int bb1 = r1 >> 11, s1 = r1 & 2047;
                const int bb2 = r2 >> 11, s2 = r2 & 2047;
                float2 v1 = make_float2((acc[mi][ni][0] + b0) * scale,
                                        (acc[mi][ni][1] + b1) * scale);
                float2 v2 = make_float2((acc[mi][ni][2] + b0) * scale,
                                        (acc[mi][ni][3] + b1) * scale);
                if (which == 2) {
                    // g_v is [b][n][d][s]
                    float* p1 = g_v + ((long)(bb1 * NH + hn) * DD + d) * SS + s1;
                    float* p2 = g_v + ((long)(bb2 * NH + hn) * DD + d) * SS + s2;
                    p1[0] = v1.x; p1[SS] = v1.y;
                    p2[0] = v2.x; p2[SS] = v2.y;
                } else {
                    float* dst0 = (which == 0) ? g_q : g_k;
                    *(float2*)(dst0 + (((long)(bb1 * NH + hn) * SS) + s1) * DD + d) = v1;
                    *(float2*)(dst0 + (((long)(bb2 * NH + hn) * SS) + s2) * DD + d) = v2;
                }
            } else {
                float2 v1 = make_float2(acc[mi][ni][0] + b0, acc[mi][ni][1] + b1);
                float2 v2 = make_float2(acc[mi][ni][2] + b0, acc[mi][ni][3] + b1);
                *(float2*)(Y + (long)r1 * HH + col) = v1;
                *(float2*)(Y + (long)r2 * HH + col) = v2;
            }
        }
    }
}

// ---------------------------------------------------------------------------
// Kernel 2: causal flash attention, tf32 mma.sync + ldmatrix fragment loads.
// ---------------------------------------------------------------------------
__global__ __launch_bounds__(256) void flash_attn_mma()
{
    __shared__ float Ks[32][68];    // [kv][d]   stride 68 % 32 == 4 -> LDSM ok
    __shared__ float Vs[64][36];    // [d][kv]   stride 36 % 32 == 4 -> LDSM ok
    __shared__ float Ps[128][36];   // [qrow][kv]

    const int t    = threadIdx.x;
    const int wid  = t >> 5;
    const int lane = t & 31;
    const int g    = lane >> 2;
    const int c    = lane & 3;
    const int bn   = blockIdx.y;        // b*16+n
    const int q0   = blockIdx.x * 128;
    const int wr   = wid * 16;

    const int a_row = ((lane >> 3) & 1) * 8 + (lane & 7);
    const int a_kof = (lane >> 4) * 4;
    const int b_row = ((lane >> 4) & 1) * 8 + (lane & 7);
    const int b_kof = ((lane >> 3) & 1) * 4;

    const float* Qp = g_q + (long)bn * SS * DD;
    const float* Kp = g_k + (long)bn * SS * DD;
    const float* Vp = g_v + (long)bn * DD * SS;   // [d][s]

    // Q fragments (tf32), loaded once
    uint32_t Qf[8][4];
    {
        const float* qr0 = Qp + (long)(q0 + wr + g) * DD;
        const float* qr1 = qr0 + 8 * DD;
#pragma unroll
        for (int kc = 0; kc < 8; kc++) {
            Qf[kc][0] = f2tf32(qr0[kc * 8 + c]);
            Qf[kc][1] = f2tf32(qr1[kc * 8 + c]);
            Qf[kc][2] = f2tf32(qr0[kc * 8 + c + 4]);
            Qf[kc][3] = f2tf32(qr1[kc * 8 + c + 4]);
        }
    }

    float O[8][4];
#pragma unroll
    for (int dn = 0; dn < 8; dn++)
#pragma unroll
        for (int k = 0; k < 4; k++) O[dn][k] = 0.f;
    float m0v = -1e30f, m1v = -1e30f, l0 = 0.f, l1 = 0.f;

    const int r0g = q0 + wr + g;
    const int r1g = r0g + 8;
    const int nkt = (q0 + 128) >> 5;

    for (int kt = 0; kt < nkt; kt++) {
        const int k0 = kt * 32;
        __syncthreads();
        // K tile: [kv][d] rows; V tile: [d][kv] rows (from d-major g_v)
#pragma unroll
        for (int p = 0; p < 2; p++) {
            int slot = t + p * 256;
            {   // K: 32 rows x 16 float4
                int row = slot >> 4;
                int c4  = (slot & 15) * 4;
                float4 kv = *(const float4*)(Kp + (long)(k0 + row) * DD + c4);
                Ks[row][c4 + 0] = tf32f(kv.x); Ks[row][c4 + 1] = tf32f(kv.y);
                Ks[row][c4 + 2] = tf32f(kv.z); Ks[row][c4 + 3] = tf32f(kv.w);
            }
            {   // V: 64 rows (d) x 8 float4 (kv)
                int row = slot >> 3;          // d
                int s4  = (slot & 7) * 4;     // kv offset
                float4 vv = *(const float4*)(Vp + (long)row * SS + k0 + s4);
                float4 w = make_float4(tf32f(vv.x), tf32f(vv.y), tf32f(vv.z), tf32f(vv.w));
                *(float4*)&Vs[row][s4] = w;
            }
        }
        __syncthreads();

        // S = Q K^T
        float S[4][4];
#pragma unroll
        for (int ni = 0; ni < 4; ni++)
#pragma unroll
            for (int k = 0; k < 4; k++) S[ni][k] = 0.f;
#pragma unroll
        for (int kc = 0; kc < 8; kc++) {
            uint32_t bt[4];
            ldsm4(bt, &Ks[b_row][kc * 8 + b_kof]);        // kv 0..15
            mma_tf32(S[0], Qf[kc], &bt[0]);
            mma_tf32(S[1], Qf[kc], &bt[2]);
            ldsm4(bt, &Ks[16 + b_row][kc * 8 + b_kof]);   // kv 16..31
            mma_tf32(S[2], Qf[kc], &bt[0]);
            mma_tf32(S[3], Qf[kc], &bt[2]);
        }

        // causal mask + row max
        float mx0 = m0v, mx1 = m1v;
#pragma unroll
        for (int ni = 0; ni < 4; ni++) {
            const int col0 = k0 + ni * 8 + 2 * c;
            const int col1 = col0 + 1;
            if (col0 > r0g) S[ni][0] = -1e30f;
            if (col1 > r0g) S[ni][1] = -1e30f;
            if (col0 > r1g) S[ni][2] = -1e30f;
            if (col1 > r1g) S[ni][3] = -1e30f;
            mx0 = fmaxf(mx0, fmaxf(S[ni][0], S[ni][1]));
            mx1 = fmaxf(mx1, fmaxf(S[ni][2], S[ni][3]));
        }
        mx0 = fmaxf(mx0, __shfl_xor_sync(0xffffffffu, mx0, 1));
        mx0 = fmaxf(mx0, __shfl_xor_sync(0xffffffffu, mx0, 2));
        mx1 = fmaxf(mx1, __shfl_xor_sync(0xffffffffu, mx1, 1));
        mx1 = fmaxf(mx1, __shfl_xor_sync(0xffffffffu, mx1, 2));

        const float a0 = __expf(m0v - mx0);
        const float a1 = __expf(m1v - mx1);
        m0v = mx0; m1v = mx1;

        float rs0 = 0.f, rs1 = 0.f;
#pragma unroll
        for (int ni = 0; ni < 4; ni++) {
            float p00 = __expf(S[ni][0] - mx0);
            float p01 = __expf(S[ni][1] - mx0);
            float p10 = __expf(S[ni][2] - mx1);
            float p11 = __expf(S[ni][3] - mx1);
            rs0 += p00 + p01; rs1 += p10 + p11;
            *(float2*)&Ps[wr + g][ni * 8 + 2 * c]     = make_float2(tf32f(p00), tf32f(p01));
            *(float2*)&Ps[wr + g + 8][ni * 8 + 2 * c] = make_float2(tf32f(p10), tf32f(p11));
        }
        rs0 += __shfl_xor_sync(0xffffffffu, rs0, 1);
        rs0 += __shfl_xor_sync(0xffffffffu, rs0, 2);
        rs1 += __shfl_xor_sync(0xffffffffu, rs1, 1);
        rs1 += __shfl_xor_sync(0xffffffffu, rs1, 2);
        l0 = l0 * a0 + rs0;
        l1 = l1 * a1 + rs1;

#pragma unroll
        for (int dn = 0; dn < 8; dn++) {
            O[dn][0] *= a0; O[dn][1] *= a0;
            O[dn][2] *= a1; O[dn][3] *= a1;
        }
        __syncwarp();   // order Ps stores before ldmatrix reads (warp-private rows)

        // O += P @ V
#pragma unroll
        for (int j = 0; j < 4; j++) {
            uint32_t Af[4];
            ldsm4(Af, &Ps[wr + a_row][j * 8 + a_kof]);
#pragma unroll
            for (int dnp = 0; dnp < 4; dnp++) {
                uint32_t bt[4];
                ldsm4(bt, &Vs[dnp * 16 + b_row][j * 8 + b_kof]);
                mma_tf32(O[dnp * 2 + 0], Af, &bt[0]);
                mma_tf32(O[dnp * 2 + 1], Af, &bt[2]);
            }
        }
    }

    // epilogue: O /= l, write g_o[b*s][hn*64+d]
    const float inv0 = 1.0f / l0;
    const float inv1 = 1.0f / l1;
    const int b  = bn >> 4;
    const int hn = bn & 15;
    float* orow0 = g_o + (long)(b * SS + r0g) * HH + hn * DD;
    float* orow1 = orow0 + 8 * HH;
#pragma unroll
    for (int dn = 0; dn < 8; dn++) {
        *(float2*)(orow0 + dn * 8 + 2 * c) = make_float2(O[dn][0] * inv0, O[dn][1] * inv0);
        *(float2*)(orow1 + dn * 8 + 2 * c) = make_float2(O[dn][2] * inv1, O[dn][3] * inv1);
    }
}

// ---------------------------------------------------------------------------
extern "C" void kernel_launch(void* const* d_in, const int* in_sizes, int n_in,
                              void* d_out, int out_size)
{
    const float* hs    = (const float*)d_in[0];  // [B,S,H]
    const float* w_in  = (const float*)d_in[1];  // [3H,H]
    const float* b_in  = (const float*)d_in[2];  // [3H]
    const float* w_out = (const float*)d_in[3];  // [H,H]
    const float* b_out = (const float*)d_in[4];  // [H]
    float* out = (float*)d_out;                  // [B,S,H]

    (void)in_sizes; (void)n_in; (void)out_size;

    gemm_mma<0><<<dim3(K3H / NT, MM / MT), 256>>>(hs, w_in, b_in, nullptr);
    flash_attn_mma<<<dim3(SS / 128, BB * NH), 256>>>();
    gemm_mma<1><<<dim3(HH / NT, MM / MT), 256>>>(nullptr, w_out, b_out, out);
}